// round 5
// baseline (speedup 1.0000x reference)
#include <cuda_runtime.h>
#include <stdint.h>

// Problem constants (fixed by the reference):
//   B=16, L=512, NSESS=4, S=512, H=512
// Logical inputs (identified by element count, order-invariant):
//   session_repre        (B,4,S,H) f32        -> 8,388,608 elems (unique)
//   state_transition_mat (B,L,5)   int64/int32 -> 40,960 elems (unique)
// Output: (B, L, 5, H) f32
//
// out[b,l,j,:] = session_repre[b, sess_idx[j], stm[b,l,j]-1, :]
//   with sess_idx = {3,0,1,2,3}
// out[b,l,0,:] = mean_{j=0..3} gathered[b,l,j,:]
//
// R5: BOTH directions on the TMA bulk engine. Each gathered row is a 2KB
// contiguous 1D cp.async.bulk G2S; rows 1-4 go back out via one bulk S2G
// without ever touching registers/L1tex. Only the pooled row uses LDS/FFMA.

#define B_DIM 16
#define L_DIM 512
#define S_DIM 512
#define H_DIM 512
#define H4        (H_DIM / 4)          // 128 float4 per row
#define ROW_BYTES (H_DIM * 4)          // 2048
#define TILE_BYTES (5 * ROW_BYTES)     // 10240

__global__ void __launch_bounds__(128, 8)
state_matrix_encoder_kernel(const float* __restrict__ sess,
                            const int* __restrict__ stm32,
                            float* __restrict__ out) {
    __shared__ __align__(128) float tile[5 * H_DIM];   // 10 KB staging
    __shared__ __align__(8) unsigned long long mbar;

    const int bl = blockIdx.x;              // 0 .. B*L-1
    const int b  = bl >> 9;                 // / L_DIM
    const int t  = threadIdx.x;             // 0..127

    const uint32_t mbar_addr = (uint32_t)__cvta_generic_to_shared(&mbar);
    const uint32_t tile_addr = (uint32_t)__cvta_generic_to_shared(tile);

    if (t == 0) {
        asm volatile("mbarrier.init.shared.b64 [%0], 1;" :: "r"(mbar_addr) : "memory");
    }
    __syncthreads();

    if (t == 0) {
        // Index dtype detection: values in [1,512] (nonzero). int64 LE ->
        // word[1] = high word of idx0 = 0; int32 -> word[1] = idx1 != 0.
        const int stride = (stm32[1] == 0) ? 2 : 1;
        const int base = bl * 5 * stride;
        // sess_idx = {3,0,1,2,3}; row address in floats
        const size_t bbase = (size_t)b * 4 * S_DIM;
        #pragma unroll
        for (int j = 0; j < 5; j++) {
            const int sidx = (j == 0) ? 3 : (j - 1);
            const int p = stm32[base + j * stride] - 1;
            const float* src = sess + (bbase + (size_t)sidx * S_DIM + p) * H_DIM;
            asm volatile(
                "cp.async.bulk.shared::cta.global.mbarrier::complete_tx::bytes "
                "[%0], [%1], %2, [%3];"
                :: "r"(tile_addr + j * ROW_BYTES), "l"(src),
                   "r"(ROW_BYTES), "r"(mbar_addr) : "memory");
        }
        asm volatile(
            "mbarrier.arrive.expect_tx.shared.b64 _, [%0], %1;"
            :: "r"(mbar_addr), "r"(TILE_BYTES) : "memory");
    }

    // All threads wait for the 5 bulk loads (acquire so LDS below is ordered).
    {
        uint32_t done;
        asm volatile(
            "{\n\t.reg .pred p;\n\t"
            "mbarrier.try_wait.parity.acquire.cta.shared::cta.b64 p, [%1], %2;\n\t"
            "selp.b32 %0, 1, 0, p;\n\t}"
            : "=r"(done) : "r"(mbar_addr), "r"(0) : "memory");
        if (!done) {
            asm volatile(
                "{\n\t.reg .pred P1;\n\t"
                "WAIT_LOOP_%=:\n\t"
                "mbarrier.try_wait.parity.acquire.cta.shared::cta.b64 P1, [%0], %1, 0x989680;\n\t"
                "@P1 bra.uni WAIT_DONE_%=;\n\t"
                "bra.uni WAIT_LOOP_%=;\n\t"
                "WAIT_DONE_%=:\n\t}"
                :: "r"(mbar_addr), "r"(0) : "memory");
        }
    }

    // Pooled row: mean of rows 0..3, overwrite row 0 in SMEM.
    {
        float4* t4 = (float4*)tile;
        const float4 a = t4[0 * H4 + t];
        const float4 c1 = t4[1 * H4 + t];
        const float4 c2 = t4[2 * H4 + t];
        const float4 c3 = t4[3 * H4 + t];
        float4 pooled;
        pooled.x = (a.x + c1.x + c2.x + c3.x) * 0.25f;
        pooled.y = (a.y + c1.y + c2.y + c3.y) * 0.25f;
        pooled.z = (a.z + c1.z + c2.z + c3.z) * 0.25f;
        pooled.w = (a.w + c1.w + c2.w + c3.w) * 0.25f;
        t4[0 * H4 + t] = pooled;
    }
    __syncthreads();

    // Order generic-proxy STS before async-proxy bulk store.
    asm volatile("fence.proxy.async.shared::cta;" ::: "memory");

    if (t == 0) {
        float* dst = out + (size_t)bl * 5 * H_DIM;
        asm volatile(
            "cp.async.bulk.global.shared::cta.bulk_group [%0], [%1], %2;"
            :: "l"(dst), "r"(tile_addr), "r"(TILE_BYTES) : "memory");
        asm volatile("cp.async.bulk.commit_group;" ::: "memory");
        // Keep CTA (and its smem) alive until the bulk engine read completes.
        asm volatile("cp.async.bulk.wait_group.read 0;" ::: "memory");
    }
}

extern "C" void kernel_launch(void* const* d_in, const int* in_sizes, int n_in,
                              void* d_out, int out_size) {
    // Order-invariant input identification by element count.
    const float* sess  = nullptr;
    const int*   stm32 = nullptr;
    for (int i = 0; i < n_in; i++) {
        if (in_sizes[i] == B_DIM * 4 * S_DIM * H_DIM) sess  = (const float*)d_in[i];
        else if (in_sizes[i] == B_DIM * L_DIM * 5)    stm32 = (const int*)d_in[i];
    }

    state_matrix_encoder_kernel<<<B_DIM * L_DIM, 128>>>(sess, stm32, (float*)d_out);
}